// round 15
// baseline (speedup 1.0000x reference)
#include <cuda_runtime.h>
#include <cstdint>

// Problem constants
#define NG   40      // groups
#define CPG  8       // channels per group (320/40)
#define ND   48      // disparity bins
#define NH   128
#define NW   240
#define NCC  12      // concat channels per tensor
#define PAD  48      // left zero-pad for shifted tgt (>= max d)
#define TROW (NW + PAD)   // 288 floats per padded tgt row
#define HW   (NH * NW)

#define NTILES   (NG * NH)         // 5120 (g,h) tiles
#define GWC_GRID 608               // tile-strided; ~4 CTAs/SM if regs allow
#define BUF_FLT  (CPG * NW + CPG * TROW)   // 4224 floats per buffer

// -------------------- cp.async helpers --------------------
__device__ __forceinline__ void cp_async16(void* smem_dst, const void* gmem_src) {
    uint32_t s = (uint32_t)__cvta_generic_to_shared(smem_dst);
    asm volatile("cp.async.cg.shared.global [%0], [%1], 16;\n" ::
                 "r"(s), "l"(gmem_src));
}
__device__ __forceinline__ void cp_commit() {
    asm volatile("cp.async.commit_group;\n");
}
template <int N>
__device__ __forceinline__ void cp_wait() {
    asm volatile("cp.async.wait_group %0;\n" :: "n"(N));
}

// ---------------------------------------------------------------------------
// Kernel 1: groupwise-correlation volume — persistent CTAs, double-buffered
// cp.async pipeline over (g, h) tiles (R11 structure, proven -21 us), with
// the 4w x 8d x k=2 register tile (R8 structure) to cut LDS traffic from
// 24 B/out to 16 B/out: per (k,c) one ref LDS.128 + three window LDS.128
// serve 32 outputs. 1/8 scale applied in the store epilogue.
// ---------------------------------------------------------------------------
__global__ __launch_bounds__(192) void gwc_kernel(const float* __restrict__ ref,
                                                  const float* __restrict__ tgt,
                                                  float* __restrict__ out) {
    // per buffer: sref = [0,1920), stgt = [1920, 1920+2304) (padded rows)
    __shared__ __align__(16) float sbuf[2][BUF_FLT];

    const int tid = threadIdx.x;

    // Zero the pad regions of both buffers once (fills never touch them).
    for (int b = 0; b < 2; b++)
        for (int i = tid; i < CPG * (PAD / 4); i += 192) {
            int c = i / (PAD / 4), pq = i % (PAD / 4);
            *(float4*)(&sbuf[b][CPG * NW + c * TROW + pq * 4]) =
                make_float4(0.f, 0.f, 0.f, 0.f);
        }

    const int stride = gridDim.x;
    int t = blockIdx.x;

    // Fill: tile tt -> buffer buf (ref 480 f4 + tgt 480 f4, cp.async)
    auto fill = [&](float* buf, int tt) {
        const int g = tt / NH, h = tt % NH;
        const float* gr = ref + ((size_t)(g * CPG) * NH + h) * NW;
        const float* gt = tgt + ((size_t)(g * CPG) * NH + h) * NW;
        float* sr = buf;
        float* st = buf + CPG * NW;
        for (int i = tid; i < CPG * 60; i += 192) {
            int c = i / 60, wq = i % 60;
            cp_async16(sr + c * NW + wq * 4,         gr + (size_t)c * HW + wq * 4);
            cp_async16(st + c * TROW + PAD + wq * 4, gt + (size_t)c * HW + wq * 4);
        }
    };

    // Prologue: start fill of first tile.
    if (t < NTILES) fill(sbuf[0], t);
    cp_commit();

    const int wq   = tid & 63;    // 0..59 active per 64-thread slice
    const int dgrp = tid >> 6;    // 0..2
    const bool active = (wq < NW / 4);
    const int w0 = wq * 4;

    int p = 0;
    for (; t < NTILES; t += stride) {
        const int tn = t + stride;
        if (tn < NTILES) {            // stream next tile into the other buffer
            fill(sbuf[p ^ 1], tn);
            cp_commit();
            cp_wait<1>();             // current tile's fill complete
        } else {
            cp_wait<0>();
        }
        __syncthreads();              // fills visible to all threads

        if (active) {
            const int g = t / NH, h = t % NH;
            const float* srb = sbuf[p] + w0;                      // sref base
            const float* stb = sbuf[p] + CPG * NW + PAD + w0;     // stgt base
            float* outb = out + (size_t)g * ND * HW + (size_t)h * NW + w0;

#pragma unroll
            for (int k = 0; k < 2; k++) {
                const int d0 = (dgrp + 3 * k) * 8;  // d-octets 0..5 -> 48 d
                float acc[8][4] = {};
#pragma unroll
                for (int c = 0; c < CPG; c++) {
                    float4 rv = *(const float4*)(srb + c * NW);
                    float rr[4] = {rv.x, rv.y, rv.z, rv.w};
                    // window tgt[w0-d0-8 .. w0-d0+3], 16B-aligned
                    const float* tp = stb + c * TROW - d0 - 8;
                    float4 v0 = *(const float4*)tp;
                    float4 v1 = *(const float4*)(tp + 4);
                    float4 v2 = *(const float4*)(tp + 8);
                    float wv[12] = {v0.x, v0.y, v0.z, v0.w,
                                    v1.x, v1.y, v1.z, v1.w,
                                    v2.x, v2.y, v2.z, v2.w};
#pragma unroll
                    for (int j = 0; j < 8; j++)
#pragma unroll
                        for (int i = 0; i < 4; i++)
                            acc[j][i] += rr[i] * wv[i + 8 - j];
                }
#pragma unroll
                for (int j = 0; j < 8; j++) {
                    float4 o = make_float4(acc[j][0] * 0.125f,
                                           acc[j][1] * 0.125f,
                                           acc[j][2] * 0.125f,
                                           acc[j][3] * 0.125f);
                    *(float4*)(outb + (size_t)(d0 + j) * HW) = o;
                }
            }
        }
        __syncthreads();              // reads done before buffer is refilled
        p ^= 1;
    }
}

// ---------------------------------------------------------------------------
// Kernel 2: concat volume. One block per (c_out, d); d uniform per block.
// ---------------------------------------------------------------------------
template <int S>
__device__ __forceinline__ float4 shift_sel(float4 lo, float4 hi) {
    if (S == 0) return hi;
    if (S == 1) return make_float4(lo.w, hi.x, hi.y, hi.z);
    if (S == 2) return make_float4(lo.z, lo.w, hi.x, hi.y);
    return make_float4(lo.y, lo.z, lo.w, hi.x);
}

template <int S>
__device__ __forceinline__ void tgt_loop(const float* __restrict__ p, int o0, int o1,
                                         float* __restrict__ ob, int hy,
                                         bool k0, bool k1, bool k2, bool k3) {
#pragma unroll 4
    for (int h = hy; h < NH; h += 4) {
        float4 lo = (S != 0) ? *(const float4*)(p + (size_t)h * NW + o0)
                             : make_float4(0.f, 0.f, 0.f, 0.f);
        float4 hi = *(const float4*)(p + (size_t)h * NW + o1);
        float4 o = shift_sel<S>(lo, hi);
        o.x = k0 ? o.x : 0.f;
        o.y = k1 ? o.y : 0.f;
        o.z = k2 ? o.z : 0.f;
        o.w = k3 ? o.w : 0.f;
        *(float4*)(ob + (size_t)h * NW) = o;
    }
}

__global__ __launch_bounds__(256) void concat_kernel(const float* __restrict__ refc,
                                                     const float* __restrict__ tgtc,
                                                     float* __restrict__ out) {
    const int c   = blockIdx.x / ND;   // 0..23
    const int d   = blockIdx.x % ND;   // uniform per block
    const int tid = threadIdx.x;
    const int wq  = tid & 63;          // 0..59 active
    const int hy  = tid >> 6;          // 0..3
    if (wq >= NW / 4) return;
    const int w0 = wq * 4;

    const bool k0 = (w0 + 0 >= d), k1 = (w0 + 1 >= d),
               k2 = (w0 + 2 >= d), k3 = (w0 + 3 >= d);

    float* ob = out + ((size_t)(NG + c) * ND + d) * HW + w0;

    if (c < NCC) {
        const float* p = refc + (size_t)c * HW + w0;
#pragma unroll 4
        for (int h = hy; h < NH; h += 4) {
            float4 v = *(const float4*)(p + (size_t)h * NW);
            v.x = k0 ? v.x : 0.f;
            v.y = k1 ? v.y : 0.f;
            v.z = k2 ? v.z : 0.f;
            v.w = k3 ? v.w : 0.f;
            *(float4*)(ob + (size_t)h * NW) = v;
        }
    } else {
        const int s   = d & 3;
        const int dlo = d - s;
        const float* p = tgtc + (size_t)(c - NCC) * HW;
        const int a0 = w0 - dlo - 4;
        const int o0 = a0 < 0 ? 0 : a0;          // clamped aligned bases
        const int o1 = a0 + 4 < 0 ? 0 : a0 + 4;
        switch (s) {
            case 0:  tgt_loop<0>(p, o0, o1, ob, hy, k0, k1, k2, k3); break;
            case 1:  tgt_loop<1>(p, o0, o1, ob, hy, k0, k1, k2, k3); break;
            case 2:  tgt_loop<2>(p, o0, o1, ob, hy, k0, k1, k2, k3); break;
            default: tgt_loop<3>(p, o0, o1, ob, hy, k0, k1, k2, k3); break;
        }
    }
}

// ---------------------------------------------------------------------------
extern "C" void kernel_launch(void* const* d_in, const int* in_sizes, int n_in,
                              void* d_out, int out_size) {
    (void)in_sizes; (void)n_in; (void)out_size;
    const float* ref_gwc = (const float*)d_in[0];
    const float* tgt_gwc = (const float*)d_in[1];
    const float* ref_c   = (const float*)d_in[2];
    const float* tgt_c   = (const float*)d_in[3];
    float* out = (float*)d_out;

    // concat first so ncu -s 5 -c 1 keeps landing on gwc_kernel.
    concat_kernel<<<2 * NCC * ND, 256>>>(ref_c, tgt_c, out);
    gwc_kernel<<<GWC_GRID, 192>>>(ref_gwc, tgt_gwc, out);
}